// round 1
// baseline (speedup 1.0000x reference)
#include <cuda_runtime.h>
#include <cstdio>

// ---------------------------------------------------------------------------
// Problem constants
// ---------------------------------------------------------------------------
#define BROWS 32768
#define NUM_EXPERTS 10
#define NUM_LEVELS 4
#define CBK 256
#define ZD 128
#define BETA 0.001f

// Output layout (float32, tuple flattened in order: out, loss, indices, x_q)
#define OUT_OFF  0
#define OUT_LEN  (32768 * 768)
#define LOSS_OFF (OUT_OFF + OUT_LEN)            // 25165824
#define IDX_OFF  (LOSS_OFF + 1)                 // 25165825
#define IDX_LEN  (32768 * 4)
#define XQ_OFF   (IDX_OFF + IDX_LEN)            // 25296897 (odd -> scalar copies only)
#define XQ_LEN   (32768 * 128)

// ---------------------------------------------------------------------------
// Device scratch (static allocations are the only legal scratch)
// ---------------------------------------------------------------------------
__device__ float g_buf0[32768u * 2048u];   // 256 MB ping
__device__ float g_buf1[32768u * 1024u];   // 128 MB pong
__device__ float g_res [32768 * ZD];       // residual (initialized by enc L3)
__device__ float g_xq  [32768 * ZD];       // qsum (aligned copy of x_q)
__device__ float g_lossbuf[32768];
__device__ int   g_counts[NUM_EXPERTS];
__device__ int   g_cursor[NUM_EXPERTS];
__device__ int   g_offsets[NUM_EXPERTS + 1];
__device__ int   g_perm[32768];

// ---------------------------------------------------------------------------
// Classic 128x128x8 SIMT SGEMM, fused bias (+ optional relu).
// A: [M,K] row-major, W: [K,N] row-major, C: [M,N].
// Requires: M%128==0, N%128==0, K%8==0 (true for all 8 layers here).
// ---------------------------------------------------------------------------
template <bool RELU>
__global__ __launch_bounds__(256, 2)
void sgemm_bias(const float* __restrict__ A, const float* __restrict__ W,
                const float* __restrict__ bias, float* __restrict__ C,
                int M, int N, int K)
{
    __shared__ float As[8][128];
    __shared__ float Bs[8][128];

    const int t  = threadIdx.x;
    const int bm = blockIdx.y;
    const int bn = blockIdx.x;
    const int tx = t & 15;      // 0..15  (8 cols each)
    const int ty = t >> 4;      // 0..15  (8 rows each)

    // A tile loader: thread -> (row = t>>1, 4 floats at col (t&1)*4)
    const int arow = t >> 1;
    const int acol = (t & 1) * 4;
    const float* Ag = A + (bm * 128 + arow) * K + acol;

    // W tile loader: thread -> (row = t>>5, 4 floats at col (t&31)*4)
    const int brow = t >> 5;
    const int bcol = (t & 31) * 4;
    const float* Wg = W + brow * N + bn * 128 + bcol;

    float acc[8][8];
#pragma unroll
    for (int i = 0; i < 8; i++)
#pragma unroll
        for (int j = 0; j < 8; j++) acc[i][j] = 0.f;

    for (int k0 = 0; k0 < K; k0 += 8) {
        float4 av = *(const float4*)(Ag + k0);
        float4 wv = *(const float4*)(Wg + k0 * N);

        As[acol + 0][arow] = av.x;
        As[acol + 1][arow] = av.y;
        As[acol + 2][arow] = av.z;
        As[acol + 3][arow] = av.w;
        *(float4*)&Bs[brow][bcol] = wv;
        __syncthreads();

#pragma unroll
        for (int k = 0; k < 8; k++) {
            float a[8], b[8];
            *(float4*)&a[0] = *(const float4*)&As[k][ty * 8];
            *(float4*)&a[4] = *(const float4*)&As[k][ty * 8 + 4];
            *(float4*)&b[0] = *(const float4*)&Bs[k][tx * 8];
            *(float4*)&b[4] = *(const float4*)&Bs[k][tx * 8 + 4];
#pragma unroll
            for (int i = 0; i < 8; i++)
#pragma unroll
                for (int j = 0; j < 8; j++)
                    acc[i][j] += a[i] * b[j];
        }
        __syncthreads();
    }

    // Epilogue: bias + optional relu, vectorized stores
    const int crow0 = bm * 128 + ty * 8;
    const int ccol0 = bn * 128 + tx * 8;
    float bb[8];
#pragma unroll
    for (int j = 0; j < 8; j++) bb[j] = bias[ccol0 + j];

#pragma unroll
    for (int i = 0; i < 8; i++) {
        float v[8];
#pragma unroll
        for (int j = 0; j < 8; j++) {
            float x = acc[i][j] + bb[j];
            if (RELU) x = fmaxf(x, 0.f);
            v[j] = x;
        }
        float* cp = C + (crow0 + i) * N + ccol0;
        *(float4*)(cp)     = *(float4*)&v[0];
        *(float4*)(cp + 4) = *(float4*)&v[4];
    }
}

// ---------------------------------------------------------------------------
// Expert counting-sort of rows
// ---------------------------------------------------------------------------
__global__ void k_zero_counts() {
    int t = threadIdx.x;
    if (t < NUM_EXPERTS) { g_counts[t] = 0; g_cursor[t] = 0; }
}
__global__ void k_hist(const int* __restrict__ labels) {
    int i = blockIdx.x * blockDim.x + threadIdx.x;
    if (i < BROWS) atomicAdd(&g_counts[labels[i]], 1);
}
__global__ void k_scan() {
    if (threadIdx.x == 0) {
        int s = 0;
        for (int e = 0; e < NUM_EXPERTS; e++) { g_offsets[e] = s; s += g_counts[e]; }
        g_offsets[NUM_EXPERTS] = s;
    }
}
__global__ void k_scatter(const int* __restrict__ labels) {
    int i = blockIdx.x * blockDim.x + threadIdx.x;
    if (i < BROWS) {
        int e = labels[i];
        int p = atomicAdd(&g_cursor[e], 1);
        g_perm[g_offsets[e] + p] = i;
    }
}
__global__ void k_rq_init() {
    int i = blockIdx.x * blockDim.x + threadIdx.x;
    if (i < BROWS * ZD) g_xq[i] = 0.f;
    if (i < BROWS)      g_lossbuf[i] = 0.f;
}

// ---------------------------------------------------------------------------
// One residual-quantization level. Grid: (ceil(B/32), NUM_EXPERTS).
// Block loads codebook[level][expert] (256x128) into padded SMEM (129 stride
// to kill the 32-way bank conflict of the naive 128 stride), processes 32
// expert-local rows: 256 threads = 256 candidate dots each, tree-argmin with
// first-min tie-break matching jnp.argmin, residual/qsum update, per-row loss.
// ---------------------------------------------------------------------------
__global__ void rq_level(const float* __restrict__ cb,
                         float* __restrict__ idx_out,   // d_out + IDX_OFF
                         int level)
{
    extern __shared__ float c_sh[];        // 256 * 129 floats
    __shared__ float res_sh[ZD];
    __shared__ float cn_sh[CBK];
    __shared__ float s_sc[CBK];
    __shared__ int   s_ix[CBK];
    __shared__ float s_red[4];
    __shared__ int   s_kmin;

    const int e     = blockIdx.y;
    const int start = g_offsets[e];
    const int end   = g_offsets[e + 1];
    const int rbase = start + blockIdx.x * 32;
    if (rbase >= end) return;

    const int t = threadIdx.x;

    // Load this (level, expert) codebook: 256x128 floats, pad stride 129.
    const float* cbl = cb + ((size_t)level * NUM_EXPERTS + e) * CBK * ZD;
    for (int i = t; i < (CBK * ZD) / 4; i += 256) {
        float4 v = ((const float4*)cbl)[i];
        int k = i >> 5;            // row (128/4 = 32 float4 per row)
        int j = (i & 31) << 2;     // col
        float* d = &c_sh[k * 129 + j];
        d[0] = v.x; d[1] = v.y; d[2] = v.z; d[3] = v.w;
    }
    __syncthreads();

    // Per-candidate squared norm
    {
        const float* cr = &c_sh[t * 129];
        float s = 0.f;
#pragma unroll 8
        for (int j = 0; j < ZD; j++) s += cr[j] * cr[j];
        cn_sh[t] = s;
    }
    __syncthreads();

    const int nrows = min(32, end - rbase);
    for (int i = 0; i < nrows; i++) {
        const int row = g_perm[rbase + i];
        if (t < ZD) res_sh[t] = g_res[row * ZD + t];
        __syncthreads();

        // score_k = ||c_k||^2 - 2 <res, c_k>   (argmin-equivalent to distance)
        float dot = 0.f;
        const float* cr = &c_sh[t * 129];
#pragma unroll 8
        for (int j = 0; j < ZD; j++) dot += cr[j] * res_sh[j];
        s_sc[t] = cn_sh[t] - 2.f * dot;
        s_ix[t] = t;
        __syncthreads();

        // argmin, tie -> lowest index (matches jnp.argmin)
#pragma unroll
        for (int s = 128; s > 0; s >>= 1) {
            if (t < s) {
                float sc2 = s_sc[t + s]; int ix2 = s_ix[t + s];
                if (sc2 < s_sc[t] || (sc2 == s_sc[t] && ix2 < s_ix[t])) {
                    s_sc[t] = sc2; s_ix[t] = ix2;
                }
            }
            __syncthreads();
        }
        if (t == 0) s_kmin = s_ix[0];
        __syncthreads();
        const int kmin = s_kmin;

        // Update residual / qsum; loss term = ||res_new||^2 (since res_new = -(q-res))
        float sq = 0.f;
        if (t < ZD) {
            float q  = c_sh[kmin * 129 + t];
            float nr = res_sh[t] - q;
            g_res[row * ZD + t] = nr;
            g_xq [row * ZD + t] += q;
            sq = nr * nr;
        }
#pragma unroll
        for (int o = 16; o > 0; o >>= 1) sq += __shfl_down_sync(0xffffffffu, sq, o);
        if (t < ZD && (t & 31) == 0) s_red[t >> 5] = sq;
        __syncthreads();
        if (t == 0) {
            g_lossbuf[row] += s_red[0] + s_red[1] + s_red[2] + s_red[3];
            idx_out[row * 4 + level] = (float)kmin;
        }
        __syncthreads();
    }
}

__global__ void k_loss_finish(float* __restrict__ loss_out) {
    __shared__ float sm[1024];
    float s = 0.f;
    for (int i = threadIdx.x; i < BROWS; i += 1024) s += g_lossbuf[i];
    sm[threadIdx.x] = s;
    __syncthreads();
    for (int k = 512; k > 0; k >>= 1) {
        if (threadIdx.x < k) sm[threadIdx.x] += sm[threadIdx.x + k];
        __syncthreads();
    }
    if (threadIdx.x == 0)
        loss_out[0] = sm[0] * (1.f + BETA) / ((float)BROWS * (float)ZD);
}

// x_q output region starts at an odd float offset -> scalar copy
__global__ void k_copy_xq(float* __restrict__ dst) {
    int i = blockIdx.x * blockDim.x + threadIdx.x;
    if (i < BROWS * ZD) dst[i] = g_xq[i];
}

// ---------------------------------------------------------------------------
// Launch
// ---------------------------------------------------------------------------
static inline void gemm(const float* A, const float* W, const float* b, float* C,
                        int M, int N, int K, bool relu)
{
    dim3 grid(N / 128, M / 128);
    if (relu) sgemm_bias<true ><<<grid, 256>>>(A, W, b, C, M, N, K);
    else      sgemm_bias<false><<<grid, 256>>>(A, W, b, C, M, N, K);
}

extern "C" void kernel_launch(void* const* d_in, const int* in_sizes, int n_in,
                              void* d_out, int out_size)
{
    const float* x      = (const float*)d_in[0];
    const int*   labels = (const int*)  d_in[1];
    const float* ew[4]  = {(const float*)d_in[2], (const float*)d_in[4],
                           (const float*)d_in[6], (const float*)d_in[8]};
    const float* eb[4]  = {(const float*)d_in[3], (const float*)d_in[5],
                           (const float*)d_in[7], (const float*)d_in[9]};
    const float* dw[4]  = {(const float*)d_in[10], (const float*)d_in[12],
                           (const float*)d_in[14], (const float*)d_in[16]};
    const float* db[4]  = {(const float*)d_in[11], (const float*)d_in[13],
                           (const float*)d_in[15], (const float*)d_in[17]};
    const float* cb     = (const float*)d_in[18];

    float* out = (float*)d_out;

    // Resolve device-scratch addresses
    float *buf0, *buf1, *res, *xq;
    cudaGetSymbolAddress((void**)&buf0, g_buf0);
    cudaGetSymbolAddress((void**)&buf1, g_buf1);
    cudaGetSymbolAddress((void**)&res,  g_res);
    cudaGetSymbolAddress((void**)&xq,   g_xq);

    // RQ kernel needs 132KB dynamic smem
    static const int RQ_SMEM = CBK * 129 * sizeof(float);
    cudaFuncSetAttribute(rq_level, cudaFuncAttributeMaxDynamicSharedMemorySize, RQ_SMEM);

    // ---- expert grouping ----
    k_zero_counts<<<1, 32>>>();
    k_hist   <<<BROWS / 256, 256>>>(labels);
    k_scan   <<<1, 1>>>();
    k_scatter<<<BROWS / 256, 256>>>(labels);

    // ---- encoder ----
    gemm(x,    ew[0], eb[0], buf0, BROWS, 2048, 768,  true);
    gemm(buf0, ew[1], eb[1], buf1, BROWS, 1024, 2048, true);
    gemm(buf1, ew[2], eb[2], buf0, BROWS, 512,  1024, true);
    gemm(buf0, ew[3], eb[3], res,  BROWS, 128,  512,  false);   // z -> residual

    // ---- residual quantization ----
    k_rq_init<<<(BROWS * ZD + 255) / 256, 256>>>();
    dim3 rqg((BROWS + 31) / 32, NUM_EXPERTS);
    for (int l = 0; l < NUM_LEVELS; l++)
        rq_level<<<rqg, 256, RQ_SMEM>>>(cb, out + IDX_OFF, l);
    k_loss_finish<<<1, 1024>>>(out + LOSS_OFF);
    k_copy_xq<<<(BROWS * ZD + 255) / 256, 256>>>(out + XQ_OFF);

    // ---- decoder ----
    gemm(xq,   dw[0], db[0], buf0, BROWS, 512,  128,  true);
    gemm(buf0, dw[1], db[1], buf1, BROWS, 1024, 512,  true);
    gemm(buf1, dw[2], db[2], buf0, BROWS, 2048, 1024, true);
    gemm(buf0, dw[3], db[3], out + OUT_OFF, BROWS, 768, 2048, false);
}

// round 5
// speedup vs baseline: 1.0313x; 1.0313x over previous
#include <cuda_runtime.h>
#include <cuda_bf16.h>
#include <cstdint>

// ---------------------------------------------------------------------------
// Problem constants
// ---------------------------------------------------------------------------
#define BROWS 32768
#define NUM_EXPERTS 10
#define NUM_LEVELS 4
#define CBK 256
#define ZD 128
#define BETA 0.001f

// Output layout (float32, tuple flattened: out, loss, indices, x_q)
#define OUT_OFF  0
#define LOSS_OFF (32768 * 768)
#define IDX_OFF  (LOSS_OFF + 1)
#define XQ_OFF   (IDX_OFF + 32768 * 4)

// ---------------------------------------------------------------------------
// Device scratch
// ---------------------------------------------------------------------------
__device__ float g_buf0[32768u * 2048u];
__device__ float g_buf1[32768u * 1024u];
__device__ float g_res [32768 * ZD];
__device__ float g_xq  [32768 * ZD];
__device__ float g_lossbuf[32768];
__device__ int   g_counts[NUM_EXPERTS];
__device__ int   g_cursor[NUM_EXPERTS];
__device__ int   g_offsets[NUM_EXPERTS + 1];
__device__ int   g_perm[32768];

// ---------------------------------------------------------------------------
// fp32 SIMT SGEMM (validated round 1) — used for the ENCODER, whose output z
// feeds flip-sensitive argmins and must match plain-fp32 accumulation.
// ---------------------------------------------------------------------------
template <bool RELU>
__global__ __launch_bounds__(256, 2)
void sgemm_bias(const float* __restrict__ A, const float* __restrict__ W,
                const float* __restrict__ bias, float* __restrict__ C,
                int M, int N, int K)
{
    __shared__ float As[8][128];
    __shared__ float Bs[8][128];

    const int t  = threadIdx.x;
    const int bm = blockIdx.y;
    const int bn = blockIdx.x;
    const int tx = t & 15;
    const int ty = t >> 4;

    const int arow = t >> 1;
    const int acol = (t & 1) * 4;
    const float* Ag = A + (bm * 128 + arow) * K + acol;

    const int brow = t >> 5;
    const int bcol = (t & 31) * 4;
    const float* Wg = W + brow * N + bn * 128 + bcol;

    float acc[8][8];
#pragma unroll
    for (int i = 0; i < 8; i++)
#pragma unroll
        for (int j = 0; j < 8; j++) acc[i][j] = 0.f;

    for (int k0 = 0; k0 < K; k0 += 8) {
        float4 av = *(const float4*)(Ag + k0);
        float4 wv = *(const float4*)(Wg + k0 * N);

        As[acol + 0][arow] = av.x;
        As[acol + 1][arow] = av.y;
        As[acol + 2][arow] = av.z;
        As[acol + 3][arow] = av.w;
        *(float4*)&Bs[brow][bcol] = wv;
        __syncthreads();

#pragma unroll
        for (int k = 0; k < 8; k++) {
            float a[8], b[8];
            *(float4*)&a[0] = *(const float4*)&As[k][ty * 8];
            *(float4*)&a[4] = *(const float4*)&As[k][ty * 8 + 4];
            *(float4*)&b[0] = *(const float4*)&Bs[k][tx * 8];
            *(float4*)&b[4] = *(const float4*)&Bs[k][tx * 8 + 4];
#pragma unroll
            for (int i = 0; i < 8; i++)
#pragma unroll
                for (int j = 0; j < 8; j++)
                    acc[i][j] += a[i] * b[j];
        }
        __syncthreads();
    }

    const int crow0 = bm * 128 + ty * 8;
    const int ccol0 = bn * 128 + tx * 8;
    float bb[8];
#pragma unroll
    for (int j = 0; j < 8; j++) bb[j] = bias[ccol0 + j];

#pragma unroll
    for (int i = 0; i < 8; i++) {
        float v[8];
#pragma unroll
        for (int j = 0; j < 8; j++) {
            float x = acc[i][j] + bb[j];
            if (RELU) x = fmaxf(x, 0.f);
            v[j] = x;
        }
        float* cp = C + (crow0 + i) * N + ccol0;
        *(float4*)(cp)     = *(float4*)&v[0];
        *(float4*)(cp + 4) = *(float4*)&v[4];
    }
}

// ---------------------------------------------------------------------------
// PTX helpers (arch-portable: cp.async sm_80+, tf32 mma sm_80+)
// ---------------------------------------------------------------------------
__device__ __forceinline__ uint32_t smem_u32(const void* p) {
    uint32_t a;
    asm("{ .reg .u64 t; cvta.to.shared.u64 t, %1; cvt.u32.u64 %0, t; }"
        : "=r"(a) : "l"(p));
    return a;
}
__device__ __forceinline__ void cpa16(uint32_t dst, const void* src) {
    asm volatile("cp.async.cg.shared.global [%0], [%1], 16;" :: "r"(dst), "l"(src) : "memory");
}
#define CP_COMMIT() asm volatile("cp.async.commit_group;" ::: "memory")
#define CP_WAIT1()  asm volatile("cp.async.wait_group 1;" ::: "memory")

__device__ __forceinline__ uint32_t f2tf(float x) {
    uint32_t r;
    asm("cvt.rna.tf32.f32 %0, %1;" : "=r"(r) : "f"(x));
    return r;
}
__device__ __forceinline__ void tfsplit(float x, uint32_t& hi, uint32_t& lo) {
    hi = f2tf(x);
    lo = f2tf(x - __uint_as_float(hi));
}

#define MMA_TF32(acc, a, b0, b1) \
    asm volatile("mma.sync.aligned.m16n8k8.row.col.f32.tf32.tf32.f32 " \
        "{%0,%1,%2,%3}, {%4,%5,%6,%7}, {%8,%9}, {%0,%1,%2,%3};" \
        : "+f"((acc)[0]), "+f"((acc)[1]), "+f"((acc)[2]), "+f"((acc)[3]) \
        : "r"((a)[0]), "r"((a)[1]), "r"((a)[2]), "r"((a)[3]), "r"(b0), "r"(b1))

// ---------------------------------------------------------------------------
// 3xTF32 GEMM — used for the DECODER (downstream of quantization; error is
// smooth ~1e-7, no argmin sensitivity).
// CTA tile 128x128, BK=32, 512 threads = 16 warps, warp tile 32x32.
// ---------------------------------------------------------------------------
#define ASTRIDE 36
#define BSTRIDE 132
#define ATILEB  (128 * ASTRIDE * 4)
#define BTILEB  (32 * BSTRIDE * 4)
#define STAGEB  (ATILEB + BTILEB)
#define GEMM_SMEM (2 * STAGEB)

template <bool RELU>
__global__ __launch_bounds__(512)
void tf32_gemm(const float* __restrict__ A, const float* __restrict__ W,
               const float* __restrict__ bias, float* __restrict__ C,
               int M, int N, int K)
{
    extern __shared__ char smem[];
    const uint32_t sbase = smem_u32(smem);
    const int tid  = threadIdx.x;
    const int lane = tid & 31;
    const int wid  = tid >> 5;
    const int wm   = wid & 3;
    const int wn   = wid >> 2;
    const int m0   = blockIdx.y * 128;
    const int n0   = blockIdx.x * 128;
    const int nch  = K >> 5;

    float acc[2][4][4];
#pragma unroll
    for (int a = 0; a < 2; a++)
#pragma unroll
        for (int b = 0; b < 4; b++)
#pragma unroll
            for (int c = 0; c < 4; c++) acc[a][b][c] = 0.f;

#define LOAD_STAGE(stg, k0_) do {                                              \
        uint32_t sA_ = sbase + (stg) * STAGEB;                                 \
        uint32_t sB_ = sA_ + ATILEB;                                           \
        for (int i = tid; i < 1024; i += 512) {                                \
            int ra_ = i >> 3, ca_ = i & 7;                                     \
            cpa16(sA_ + (ra_ * ASTRIDE + ca_ * 4) * 4,                         \
                  A + (size_t)(m0 + ra_) * K + (k0_) + ca_ * 4);               \
            int rb_ = i >> 5, cb_ = i & 31;                                    \
            cpa16(sB_ + (rb_ * BSTRIDE + cb_ * 4) * 4,                         \
                  W + (size_t)((k0_) + rb_) * N + n0 + cb_ * 4);               \
        }                                                                      \
    } while (0)

    LOAD_STAGE(0, 0);
    CP_COMMIT();
    if (nch > 1) LOAD_STAGE(1, 32);
    CP_COMMIT();

    const int arow = lane >> 2;
    const int acol = lane & 3;

    for (int ch = 0; ch < nch; ch++) {
        CP_WAIT1();
        __syncthreads();
        const float* As = (const float*)(smem + (ch & 1) * STAGEB);
        const float* Bs = (const float*)(smem + (ch & 1) * STAGEB + ATILEB);

#pragma unroll
        for (int kk = 0; kk < 32; kk += 8) {
            uint32_t ah[2][4], al[2][4];
#pragma unroll
            for (int mt = 0; mt < 2; mt++) {
                const int r0 = wm * 32 + mt * 16 + arow;
                const int k  = kk + acol;
                tfsplit(As[r0 * ASTRIDE + k],           ah[mt][0], al[mt][0]);
                tfsplit(As[(r0 + 8) * ASTRIDE + k],     ah[mt][1], al[mt][1]);
                tfsplit(As[r0 * ASTRIDE + k + 4],       ah[mt][2], al[mt][2]);
                tfsplit(As[(r0 + 8) * ASTRIDE + k + 4], ah[mt][3], al[mt][3]);
            }
#pragma unroll
            for (int nt = 0; nt < 4; nt++) {
                const int n = wn * 32 + nt * 8 + arow;
                const int k = kk + acol;
                uint32_t bh0, bl0, bh1, bl1;
                tfsplit(Bs[k * BSTRIDE + n],       bh0, bl0);
                tfsplit(Bs[(k + 4) * BSTRIDE + n], bh1, bl1);
#pragma unroll
                for (int mt = 0; mt < 2; mt++) {
                    MMA_TF32(acc[mt][nt], ah[mt], bh0, bh1);
                    MMA_TF32(acc[mt][nt], ah[mt], bl0, bl1);
                    MMA_TF32(acc[mt][nt], al[mt], bh0, bh1);
                }
            }
        }
        __syncthreads();
        if (ch + 2 < nch) LOAD_STAGE(ch & 1, (ch + 2) * 32);
        CP_COMMIT();
    }
#undef LOAD_STAGE

    const int gid = lane >> 2;
    const int tg  = lane & 3;
#pragma unroll
    for (int mt = 0; mt < 2; mt++) {
#pragma unroll
        for (int nt = 0; nt < 4; nt++) {
            const int col = n0 + wn * 32 + nt * 8 + tg * 2;
            const float2 bb = __ldg((const float2*)(bias + col));
#pragma unroll
            for (int h = 0; h < 2; h++) {
                const int row = m0 + wm * 32 + mt * 16 + gid + h * 8;
                float v0 = acc[mt][nt][2*h]   + bb.x;
                float v1 = acc[mt][nt][2*h+1] + bb.y;
                if (RELU) { v0 = fmaxf(v0, 0.f); v1 = fmaxf(v1, 0.f); }
                *(float2*)(C + (size_t)row * N + col) = make_float2(v0, v1);
            }
        }
    }
}

// ---------------------------------------------------------------------------
// Expert counting-sort
// ---------------------------------------------------------------------------
__global__ void k_zero_counts() {
    int t = threadIdx.x;
    if (t < NUM_EXPERTS) { g_counts[t] = 0; g_cursor[t] = 0; }
}
__global__ void k_hist(const int* __restrict__ labels) {
    int i = blockIdx.x * blockDim.x + threadIdx.x;
    if (i < BROWS) atomicAdd(&g_counts[labels[i]], 1);
}
__global__ void k_scan() {
    if (threadIdx.x == 0) {
        int s = 0;
        for (int e = 0; e < NUM_EXPERTS; e++) { g_offsets[e] = s; s += g_counts[e]; }
        g_offsets[NUM_EXPERTS] = s;
    }
}
__global__ void k_scatter(const int* __restrict__ labels) {
    int i = blockIdx.x * blockDim.x + threadIdx.x;
    if (i < BROWS) {
        int e = labels[i];
        int p = atomicAdd(&g_cursor[e], 1);
        g_perm[g_offsets[e] + p] = i;
    }
}
__global__ void k_rq_init() {
    int i = blockIdx.x * blockDim.x + threadIdx.x;
    if (i < BROWS * ZD) g_xq[i] = 0.f;
    if (i < BROWS)      g_lossbuf[i] = 0.f;
}

// ---------------------------------------------------------------------------
// Residual quantization (validated round 1)
// ---------------------------------------------------------------------------
__global__ void rq_level(const float* __restrict__ cb,
                         float* __restrict__ idx_out, int level)
{
    extern __shared__ float c_sh[];        // 256 * 129 floats
    __shared__ float res_sh[ZD];
    __shared__ float cn_sh[CBK];
    __shared__ float s_sc[CBK];
    __shared__ int   s_ix[CBK];
    __shared__ float s_red[4];
    __shared__ int   s_kmin;

    const int e     = blockIdx.y;
    const int start = g_offsets[e];
    const int end   = g_offsets[e + 1];
    const int rbase = start + blockIdx.x * 32;
    if (rbase >= end) return;

    const int t = threadIdx.x;
    const float* cbl = cb + ((size_t)level * NUM_EXPERTS + e) * CBK * ZD;
    for (int i = t; i < (CBK * ZD) / 4; i += 256) {
        float4 v = ((const float4*)cbl)[i];
        int k = i >> 5;
        int j = (i & 31) << 2;
        float* d = &c_sh[k * 129 + j];
        d[0] = v.x; d[1] = v.y; d[2] = v.z; d[3] = v.w;
    }
    __syncthreads();

    {
        const float* cr = &c_sh[t * 129];
        float s = 0.f;
#pragma unroll 8
        for (int j = 0; j < ZD; j++) s += cr[j] * cr[j];
        cn_sh[t] = s;
    }
    __syncthreads();

    const int nrows = min(32, end - rbase);
    for (int i = 0; i < nrows; i++) {
        const int row = g_perm[rbase + i];
        if (t < ZD) res_sh[t] = g_res[row * ZD + t];
        __syncthreads();

        float dot = 0.f;
        const float* cr = &c_sh[t * 129];
#pragma unroll 8
        for (int j = 0; j < ZD; j++) dot += cr[j] * res_sh[j];
        s_sc[t] = cn_sh[t] - 2.f * dot;
        s_ix[t] = t;
        __syncthreads();

#pragma unroll
        for (int s = 128; s > 0; s >>= 1) {
            if (t < s) {
                float sc2 = s_sc[t + s]; int ix2 = s_ix[t + s];
                if (sc2 < s_sc[t] || (sc2 == s_sc[t] && ix2 < s_ix[t])) {
                    s_sc[t] = sc2; s_ix[t] = ix2;
                }
            }
            __syncthreads();
        }
        if (t == 0) s_kmin = s_ix[0];
        __syncthreads();
        const int kmin = s_kmin;

        float sq = 0.f;
        if (t < ZD) {
            float q  = c_sh[kmin * 129 + t];
            float nr = res_sh[t] - q;
            g_res[row * ZD + t] = nr;
            g_xq [row * ZD + t] += q;
            sq = nr * nr;
        }
#pragma unroll
        for (int o = 16; o > 0; o >>= 1) sq += __shfl_down_sync(0xffffffffu, sq, o);
        if (t < ZD && (t & 31) == 0) s_red[t >> 5] = sq;
        __syncthreads();
        if (t == 0) {
            g_lossbuf[row] += s_red[0] + s_red[1] + s_red[2] + s_red[3];
            idx_out[row * 4 + level] = (float)kmin;
        }
        __syncthreads();
    }
}

__global__ void k_loss_finish(float* __restrict__ loss_out) {
    __shared__ float sm[1024];
    float s = 0.f;
    for (int i = threadIdx.x; i < BROWS; i += 1024) s += g_lossbuf[i];
    sm[threadIdx.x] = s;
    __syncthreads();
    for (int k = 512; k > 0; k >>= 1) {
        if (threadIdx.x < k) sm[threadIdx.x] += sm[threadIdx.x + k];
        __syncthreads();
    }
    if (threadIdx.x == 0)
        loss_out[0] = sm[0] * (1.f + BETA) / ((float)BROWS * (float)ZD);
}

__global__ void k_copy_xq(float* __restrict__ dst) {
    int i = blockIdx.x * blockDim.x + threadIdx.x;
    if (i < BROWS * ZD) dst[i] = g_xq[i];
}

// ---------------------------------------------------------------------------
// Host launch
// ---------------------------------------------------------------------------
template <bool RELU>
static void launch_sgemm(const float* A, const float* W, const float* b, float* C,
                         int M, int N, int K)
{
    dim3 grid(N / 128, M / 128);
    sgemm_bias<RELU><<<grid, 256>>>(A, W, b, C, M, N, K);
}

template <bool RELU>
static void launch_tf32(const float* A, const float* W, const float* bias,
                        float* C, int M, int N, int K)
{
    cudaFuncSetAttribute(tf32_gemm<RELU>,
                         cudaFuncAttributeMaxDynamicSharedMemorySize, GEMM_SMEM);
    dim3 g(N / 128, M / 128);
    tf32_gemm<RELU><<<g, 512, GEMM_SMEM>>>(A, W, bias, C, M, N, K);
}

extern "C" void kernel_launch(void* const* d_in, const int* in_sizes, int n_in,
                              void* d_out, int out_size)
{
    const float* x      = (const float*)d_in[0];
    const int*   labels = (const int*)  d_in[1];
    const float* ew[4]  = {(const float*)d_in[2], (const float*)d_in[4],
                           (const float*)d_in[6], (const float*)d_in[8]};
    const float* eb[4]  = {(const float*)d_in[3], (const float*)d_in[5],
                           (const float*)d_in[7], (const float*)d_in[9]};
    const float* dw[4]  = {(const float*)d_in[10], (const float*)d_in[12],
                           (const float*)d_in[14], (const float*)d_in[16]};
    const float* db[4]  = {(const float*)d_in[11], (const float*)d_in[13],
                           (const float*)d_in[15], (const float*)d_in[17]};
    const float* cb     = (const float*)d_in[18];
    float* out = (float*)d_out;

    float *buf0, *buf1, *res, *xq;
    cudaGetSymbolAddress((void**)&buf0, g_buf0);
    cudaGetSymbolAddress((void**)&buf1, g_buf1);
    cudaGetSymbolAddress((void**)&res,  g_res);
    cudaGetSymbolAddress((void**)&xq,   g_xq);

    static const int RQ_SMEM = CBK * 129 * sizeof(float);
    cudaFuncSetAttribute(rq_level, cudaFuncAttributeMaxDynamicSharedMemorySize, RQ_SMEM);

    // ---- expert grouping ----
    k_zero_counts<<<1, 32>>>();
    k_hist   <<<BROWS / 256, 256>>>(labels);
    k_scan   <<<1, 1>>>();
    k_scatter<<<BROWS / 256, 256>>>(labels);

    // ---- encoder (fp32 SIMT — flip-critical path) ----
    launch_sgemm<true >(x,    ew[0], eb[0], buf0, BROWS, 2048, 768);
    launch_sgemm<true >(buf0, ew[1], eb[1], buf1, BROWS, 1024, 2048);
    launch_sgemm<true >(buf1, ew[2], eb[2], buf0, BROWS, 512,  1024);
    launch_sgemm<false>(buf0, ew[3], eb[3], res,  BROWS, 128,  512);

    // ---- residual quantization ----
    k_rq_init<<<(BROWS * ZD + 255) / 256, 256>>>();
    dim3 rqg((BROWS + 31) / 32, NUM_EXPERTS);
    for (int l = 0; l < NUM_LEVELS; l++)
        rq_level<<<rqg, 256, RQ_SMEM>>>(cb, out + IDX_OFF, l);
    k_loss_finish<<<1, 1024>>>(out + LOSS_OFF);
    k_copy_xq<<<(BROWS * ZD + 255) / 256, 256>>>(out + XQ_OFF);

    // ---- decoder (3xTF32 tensor cores — smooth-error domain) ----
    launch_tf32<true >(xq,   dw[0], db[0], buf0, BROWS, 512,  128);
    launch_tf32<true >(buf0, dw[1], db[1], buf1, BROWS, 1024, 512);
    launch_tf32<true >(buf1, dw[2], db[2], buf0, BROWS, 2048, 1024);
    launch_tf32<false>(buf0, dw[3], db[3], out + OUT_OFF, BROWS, 768, 2048);
}

// round 6
// speedup vs baseline: 1.1188x; 1.0848x over previous
#include <cuda_runtime.h>
#include <cstdint>

// ---------------------------------------------------------------------------
// Problem constants
// ---------------------------------------------------------------------------
#define BROWS 32768
#define NUM_EXPERTS 10
#define NUM_LEVELS 4
#define CBK 256
#define ZD 128
#define BETA 0.001f

// Output layout (float32, tuple flattened: out, loss, indices, x_q)
#define OUT_OFF  0
#define LOSS_OFF (32768 * 768)
#define IDX_OFF  (LOSS_OFF + 1)
#define XQ_OFF   (IDX_OFF + 32768 * 4)

// ---------------------------------------------------------------------------
// Device scratch
// ---------------------------------------------------------------------------
__device__ float g_buf0[32768u * 2048u];   // encoder ping
__device__ float g_buf1[32768u * 1024u];   // encoder pong
__device__ float g_res [32768 * ZD];
__device__ float g_xq  [32768 * ZD];
__device__ float g_lossbuf[32768];
__device__ int   g_counts[NUM_EXPERTS];
__device__ int   g_cursor[NUM_EXPERTS];
__device__ int   g_offsets[NUM_EXPERTS + 1];
__device__ int   g_perm[32768];

// decoder hi/lo activation ping-pong + pre-split transposed weights
__device__ float g_dAh[32768u * 1024u];
__device__ float g_dAl[32768u * 1024u];
__device__ float g_dBh[32768u * 2048u];
__device__ float g_dBl[32768u * 2048u];
#define DW_TOTAL 4259840
__device__ float g_wh[DW_TOTAL];
__device__ float g_wl[DW_TOTAL];

// ---------------------------------------------------------------------------
// PTX helpers (arch-portable)
// ---------------------------------------------------------------------------
__device__ __forceinline__ uint32_t smem_u32(const void* p) {
    uint32_t a;
    asm("{ .reg .u64 t; cvta.to.shared.u64 t, %1; cvt.u32.u64 %0, t; }"
        : "=r"(a) : "l"(p));
    return a;
}
__device__ __forceinline__ void cpa16(uint32_t dst, const void* src) {
    asm volatile("cp.async.cg.shared.global [%0], [%1], 16;" :: "r"(dst), "l"(src) : "memory");
}
#define CP_COMMIT() asm volatile("cp.async.commit_group;" ::: "memory")
#define CP_WAIT1()  asm volatile("cp.async.wait_group 1;" ::: "memory")

__device__ __forceinline__ uint32_t f2tf(float x) {
    uint32_t r;
    asm("cvt.rna.tf32.f32 %0, %1;" : "=r"(r) : "f"(x));
    return r;
}

#define LDMX4(r0, r1, r2, r3, addr) \
    asm volatile("ldmatrix.sync.aligned.m8n8.x4.shared.b16 {%0,%1,%2,%3}, [%4];" \
        : "=r"(r0), "=r"(r1), "=r"(r2), "=r"(r3) : "r"(addr))

#define MMA_TF32(acc, a, b0, b1) \
    asm volatile("mma.sync.aligned.m16n8k8.row.col.f32.tf32.tf32.f32 " \
        "{%0,%1,%2,%3}, {%4,%5,%6,%7}, {%8,%9}, {%0,%1,%2,%3};" \
        : "+f"((acc)[0]), "+f"((acc)[1]), "+f"((acc)[2]), "+f"((acc)[3]) \
        : "r"((a)[0]), "r"((a)[1]), "r"((a)[2]), "r"((a)[3]), "r"(b0), "r"(b1))

// ---------------------------------------------------------------------------
// fp32 SIMT SGEMM (validated round 1) — ENCODER (flip-critical path)
// ---------------------------------------------------------------------------
template <bool RELU>
__global__ __launch_bounds__(256, 2)
void sgemm_bias(const float* __restrict__ A, const float* __restrict__ W,
                const float* __restrict__ bias, float* __restrict__ C,
                int M, int N, int K)
{
    __shared__ float As[8][128];
    __shared__ float Bs[8][128];

    const int t  = threadIdx.x;
    const int bm = blockIdx.y;
    const int bn = blockIdx.x;
    const int tx = t & 15;
    const int ty = t >> 4;

    const int arow = t >> 1;
    const int acol = (t & 1) * 4;
    const float* Ag = A + (bm * 128 + arow) * K + acol;

    const int brow = t >> 5;
    const int bcol = (t & 31) * 4;
    const float* Wg = W + brow * N + bn * 128 + bcol;

    float acc[8][8];
#pragma unroll
    for (int i = 0; i < 8; i++)
#pragma unroll
        for (int j = 0; j < 8; j++) acc[i][j] = 0.f;

    for (int k0 = 0; k0 < K; k0 += 8) {
        float4 av = *(const float4*)(Ag + k0);
        float4 wv = *(const float4*)(Wg + k0 * N);

        As[acol + 0][arow] = av.x;
        As[acol + 1][arow] = av.y;
        As[acol + 2][arow] = av.z;
        As[acol + 3][arow] = av.w;
        *(float4*)&Bs[brow][bcol] = wv;
        __syncthreads();

#pragma unroll
        for (int k = 0; k < 8; k++) {
            float a[8], b[8];
            *(float4*)&a[0] = *(const float4*)&As[k][ty * 8];
            *(float4*)&a[4] = *(const float4*)&As[k][ty * 8 + 4];
            *(float4*)&b[0] = *(const float4*)&Bs[k][tx * 8];
            *(float4*)&b[4] = *(const float4*)&Bs[k][tx * 8 + 4];
#pragma unroll
            for (int i = 0; i < 8; i++)
#pragma unroll
                for (int j = 0; j < 8; j++)
                    acc[i][j] += a[i] * b[j];
        }
        __syncthreads();
    }

    const int crow0 = bm * 128 + ty * 8;
    const int ccol0 = bn * 128 + tx * 8;
    float bb[8];
#pragma unroll
    for (int j = 0; j < 8; j++) bb[j] = bias[ccol0 + j];

#pragma unroll
    for (int i = 0; i < 8; i++) {
        float v[8];
#pragma unroll
        for (int j = 0; j < 8; j++) {
            float x = acc[i][j] + bb[j];
            if (RELU) x = fmaxf(x, 0.f);
            v[j] = x;
        }
        float* cp = C + (crow0 + i) * N + ccol0;
        *(float4*)(cp)     = *(float4*)&v[0];
        *(float4*)(cp + 4) = *(float4*)&v[4];
    }
}

// ---------------------------------------------------------------------------
// 3xTF32 GEMM v2 — DECODER. Operands pre-split to tf32-valued fp32 hi/lo
// arrays; fragments fed by ldmatrix (tf32 frag layout == m8n8.b16 x4 view).
// A: [M,K] hi/lo. W: pre-transposed [N,K] hi/lo. CTA tile 128x128, BK=32,
// 512 threads = 16 warps (4x4), warp tile 32x32. 2-stage cp.async pipeline.
// OMODE 0: fp32 C. OMODE 1: hi/lo split C (feeds next decoder layer).
// ---------------------------------------------------------------------------
#define TSTR  36                         // floats per smem row (pad)
#define SUBT  (128 * TSTR * 4)           // 18432 B per subtile
#define STAGEB (4 * SUBT)                // Ah,Al,Bh,Bl
#define GEMM_SMEM (2 * STAGEB)           // 147456 B

template <bool RELU, int OMODE>
__global__ __launch_bounds__(512)
void tf32_gemm(const float* __restrict__ Ah_, const float* __restrict__ Al_,
               const float* __restrict__ Bh_, const float* __restrict__ Bl_,
               const float* __restrict__ bias,
               float* __restrict__ Cf,
               float* __restrict__ Chi, float* __restrict__ Clo,
               int M, int N, int K)
{
    extern __shared__ char smem[];
    const uint32_t sbase = smem_u32(smem);
    const int tid  = threadIdx.x;
    const int lane = tid & 31;
    const int wid  = tid >> 5;
    const int wm   = wid & 3;
    const int wn   = wid >> 2;
    const int m0   = blockIdx.y * 128;
    const int n0   = blockIdx.x * 128;
    const int nch  = K >> 5;

    float acc[2][4][4];
#pragma unroll
    for (int a = 0; a < 2; a++)
#pragma unroll
        for (int b = 0; b < 4; b++)
#pragma unroll
            for (int c = 0; c < 4; c++) acc[a][b][c] = 0.f;

    // ldmatrix per-lane source offsets (bytes), A: x4 = {r,k},{r+8,k},{r,k+4},{r+8,k+4}
    const int a_row = (lane & 7) | (((lane >> 3) & 1) << 3);
    const int a_kp  = (lane >> 4) << 2;
    const int b_row = (lane & 7) | (((lane >> 4) & 1) << 3);
    const int b_kp  = ((lane >> 3) & 1) << 2;
    uint32_t aoff[2], boff[2];
#pragma unroll
    for (int mt = 0; mt < 2; mt++)
        aoff[mt] = ((wm * 32 + mt * 16 + a_row) * TSTR + a_kp) * 4;
#pragma unroll
    for (int p = 0; p < 2; p++)
        boff[p] = ((wn * 32 + p * 16 + b_row) * TSTR + b_kp) * 4;

#define LOAD_STAGE(stg, k0_) do {                                              \
        uint32_t s_ = sbase + (stg) * STAGEB;                                  \
        for (int i = tid; i < 1024; i += 512) {                                \
            int r_ = i >> 3, c_ = (i & 7) << 2;                                \
            uint32_t o_ = (uint32_t)(r_ * TSTR + c_) * 4;                      \
            size_t ga_ = (size_t)(m0 + r_) * K + (k0_) + c_;                   \
            size_t gb_ = (size_t)(n0 + r_) * K + (k0_) + c_;                   \
            cpa16(s_ + o_,            Ah_ + ga_);                              \
            cpa16(s_ + SUBT + o_,     Al_ + ga_);                              \
            cpa16(s_ + 2 * SUBT + o_, Bh_ + gb_);                              \
            cpa16(s_ + 3 * SUBT + o_, Bl_ + gb_);                              \
        }                                                                      \
    } while (0)

    LOAD_STAGE(0, 0);
    CP_COMMIT();
    if (nch > 1) LOAD_STAGE(1, 32);
    CP_COMMIT();

    for (int ch = 0; ch < nch; ch++) {
        CP_WAIT1();
        __syncthreads();
        const uint32_t sb = sbase + (ch & 1) * STAGEB;

#pragma unroll
        for (int kk4 = 0; kk4 < 128; kk4 += 32) {   // kk*4 bytes, kk = 0,8,16,24
            uint32_t ah[2][4], al[2][4], bh[2][4], bl[2][4];
#pragma unroll
            for (int mt = 0; mt < 2; mt++) {
                LDMX4(ah[mt][0], ah[mt][1], ah[mt][2], ah[mt][3], sb + aoff[mt] + kk4);
                LDMX4(al[mt][0], al[mt][1], al[mt][2], al[mt][3], sb + SUBT + aoff[mt] + kk4);
            }
#pragma unroll
            for (int p = 0; p < 2; p++) {
                LDMX4(bh[p][0], bh[p][1], bh[p][2], bh[p][3], sb + 2 * SUBT + boff[p] + kk4);
                LDMX4(bl[p][0], bl[p][1], bl[p][2], bl[p][3], sb + 3 * SUBT + boff[p] + kk4);
            }
#pragma unroll
            for (int mt = 0; mt < 2; mt++)
#pragma unroll
                for (int p = 0; p < 2; p++)
#pragma unroll
                    for (int q = 0; q < 2; q++) {
                        float* ac = acc[mt][p * 2 + q];
                        MMA_TF32(ac, ah[mt], bh[p][2 * q], bh[p][2 * q + 1]);
                        MMA_TF32(ac, ah[mt], bl[p][2 * q], bl[p][2 * q + 1]);
                        MMA_TF32(ac, al[mt], bh[p][2 * q], bh[p][2 * q + 1]);
                    }
        }
        __syncthreads();
        if (ch + 2 < nch) LOAD_STAGE(ch & 1, (ch + 2) * 32);
        CP_COMMIT();
    }
#undef LOAD_STAGE

    // ---- epilogue ----
    const int gid = lane >> 2;
    const int tg  = lane & 3;
#pragma unroll
    for (int mt = 0; mt < 2; mt++) {
#pragma unroll
        for (int nt = 0; nt < 4; nt++) {
            const int col = n0 + wn * 32 + nt * 8 + tg * 2;
            const float2 bb = __ldg((const float2*)(bias + col));
#pragma unroll
            for (int h = 0; h < 2; h++) {
                const int row = m0 + wm * 32 + mt * 16 + gid + h * 8;
                float v0 = acc[mt][nt][2 * h]     + bb.x;
                float v1 = acc[mt][nt][2 * h + 1] + bb.y;
                if (RELU) { v0 = fmaxf(v0, 0.f); v1 = fmaxf(v1, 0.f); }
                if (OMODE == 0) {
                    *(float2*)(Cf + (size_t)row * N + col) = make_float2(v0, v1);
                } else {
                    uint32_t h0 = f2tf(v0), h1 = f2tf(v1);
                    float l0 = __uint_as_float(f2tf(v0 - __uint_as_float(h0)));
                    float l1 = __uint_as_float(f2tf(v1 - __uint_as_float(h1)));
                    *(float2*)(Chi + (size_t)row * N + col) =
                        make_float2(__uint_as_float(h0), __uint_as_float(h1));
                    *(float2*)(Clo + (size_t)row * N + col) = make_float2(l0, l1);
                }
            }
        }
    }
}

// ---------------------------------------------------------------------------
// Preprocessing: weight transpose + tf32 split; activation split
// ---------------------------------------------------------------------------
__global__ void k_wprep32(const float* __restrict__ W, float* __restrict__ Th,
                          float* __restrict__ Tl, int K, int N)
{
    __shared__ float t[32][33];
    int n = blockIdx.x * 32 + threadIdx.x;
    int k = blockIdx.y * 32 + threadIdx.y;
    t[threadIdx.y][threadIdx.x] = W[(size_t)k * N + n];
    __syncthreads();
    int nn = blockIdx.x * 32 + threadIdx.y;
    int kk = blockIdx.y * 32 + threadIdx.x;
    float v = t[threadIdx.x][threadIdx.y];
    uint32_t h = f2tf(v);
    Th[(size_t)nn * K + kk] = __uint_as_float(h);
    Tl[(size_t)nn * K + kk] = __uint_as_float(f2tf(v - __uint_as_float(h)));
}

__global__ void k_split32(const float* __restrict__ src, float* __restrict__ hi,
                          float* __restrict__ lo, int n)
{
    int i = blockIdx.x * 256 + threadIdx.x;
    if (i < n) {
        float v = src[i];
        uint32_t h = f2tf(v);
        hi[i] = __uint_as_float(h);
        lo[i] = __uint_as_float(f2tf(v - __uint_as_float(h)));
    }
}

// ---------------------------------------------------------------------------
// Expert counting-sort
// ---------------------------------------------------------------------------
__global__ void k_zero_counts() {
    int t = threadIdx.x;
    if (t < NUM_EXPERTS) { g_counts[t] = 0; g_cursor[t] = 0; }
}
__global__ void k_hist(const int* __restrict__ labels) {
    int i = blockIdx.x * blockDim.x + threadIdx.x;
    if (i < BROWS) atomicAdd(&g_counts[labels[i]], 1);
}
__global__ void k_scan() {
    if (threadIdx.x == 0) {
        int s = 0;
        for (int e = 0; e < NUM_EXPERTS; e++) { g_offsets[e] = s; s += g_counts[e]; }
        g_offsets[NUM_EXPERTS] = s;
    }
}
__global__ void k_scatter(const int* __restrict__ labels) {
    int i = blockIdx.x * blockDim.x + threadIdx.x;
    if (i < BROWS) {
        int e = labels[i];
        int p = atomicAdd(&g_cursor[e], 1);
        g_perm[g_offsets[e] + p] = i;
    }
}
__global__ void k_rq_init() {
    int i = blockIdx.x * blockDim.x + threadIdx.x;
    if (i < BROWS * ZD) g_xq[i] = 0.f;
    if (i < BROWS)      g_lossbuf[i] = 0.f;
}

// ---------------------------------------------------------------------------
// Residual quantization (validated round 1)
// ---------------------------------------------------------------------------
__global__ void rq_level(const float* __restrict__ cb,
                         float* __restrict__ idx_out, int level)
{
    extern __shared__ float c_sh[];        // 256 * 129 floats
    __shared__ float res_sh[ZD];
    __shared__ float cn_sh[CBK];
    __shared__ float s_sc[CBK];
    __shared__ int   s_ix[CBK];
    __shared__ float s_red[4];
    __shared__ int   s_kmin;

    const int e     = blockIdx.y;
    const int start = g_offsets[e];
    const int end   = g_offsets[e + 1];
    const int rbase = start + blockIdx.x * 32;
    if (rbase >= end) return;

    const int t = threadIdx.x;
    const float* cbl = cb + ((size_t)level * NUM_EXPERTS + e) * CBK * ZD;
    for (int i = t; i < (CBK * ZD) / 4; i += 256) {
        float4 v = ((const float4*)cbl)[i];
        int k = i >> 5;
        int j = (i & 31) << 2;
        float* d = &c_sh[k * 129 + j];
        d[0] = v.x; d[1] = v.y; d[2] = v.z; d[3] = v.w;
    }
    __syncthreads();

    {
        const float* cr = &c_sh[t * 129];
        float s = 0.f;
#pragma unroll 8
        for (int j = 0; j < ZD; j++) s += cr[j] * cr[j];
        cn_sh[t] = s;
    }
    __syncthreads();

    const int nrows = min(32, end - rbase);
    for (int i = 0; i < nrows; i++) {
        const int row = g_perm[rbase + i];
        if (t < ZD) res_sh[t] = g_res[row * ZD + t];
        __syncthreads();

        float dot = 0.f;
        const float* cr = &c_sh[t * 129];
#pragma unroll 8
        for (int j = 0; j < ZD; j++) dot += cr[j] * res_sh[j];
        s_sc[t] = cn_sh[t] - 2.f * dot;
        s_ix[t] = t;
        __syncthreads();

#pragma unroll
        for (int s = 128; s > 0; s >>= 1) {
            if (t < s) {
                float sc2 = s_sc[t + s]; int ix2 = s_ix[t + s];
                if (sc2 < s_sc[t] || (sc2 == s_sc[t] && ix2 < s_ix[t])) {
                    s_sc[t] = sc2; s_ix[t] = ix2;
                }
            }
            __syncthreads();
        }
        if (t == 0) s_kmin = s_ix[0];
        __syncthreads();
        const int kmin = s_kmin;

        float sq = 0.f;
        if (t < ZD) {
            float q  = c_sh[kmin * 129 + t];
            float nr = res_sh[t] - q;
            g_res[row * ZD + t] = nr;
            g_xq [row * ZD + t] += q;
            sq = nr * nr;
        }
#pragma unroll
        for (int o = 16; o > 0; o >>= 1) sq += __shfl_down_sync(0xffffffffu, sq, o);
        if (t < ZD && (t & 31) == 0) s_red[t >> 5] = sq;
        __syncthreads();
        if (t == 0) {
            g_lossbuf[row] += s_red[0] + s_red[1] + s_red[2] + s_red[3];
            idx_out[row * 4 + level] = (float)kmin;
        }
        __syncthreads();
    }
}

__global__ void k_loss_finish(float* __restrict__ loss_out) {
    __shared__ float sm[1024];
    float s = 0.f;
    for (int i = threadIdx.x; i < BROWS; i += 1024) s += g_lossbuf[i];
    sm[threadIdx.x] = s;
    __syncthreads();
    for (int k = 512; k > 0; k >>= 1) {
        if (threadIdx.x < k) sm[threadIdx.x] += sm[threadIdx.x + k];
        __syncthreads();
    }
    if (threadIdx.x == 0)
        loss_out[0] = sm[0] * (1.f + BETA) / ((float)BROWS * (float)ZD);
}

__global__ void k_copy_xq(float* __restrict__ dst) {
    int i = blockIdx.x * blockDim.x + threadIdx.x;
    if (i < BROWS * ZD) dst[i] = g_xq[i];
}

// ---------------------------------------------------------------------------
// Host launch
// ---------------------------------------------------------------------------
template <bool RELU>
static void launch_sgemm(const float* A, const float* W, const float* b, float* C,
                         int M, int N, int K)
{
    dim3 grid(N / 128, M / 128);
    sgemm_bias<RELU><<<grid, 256>>>(A, W, b, C, M, N, K);
}

template <bool RELU, int OMODE>
static void launch_tf32(const float* ah, const float* al,
                        const float* bh, const float* bl,
                        const float* bias, float* cf, float* chi, float* clo,
                        int M, int N, int K)
{
    cudaFuncSetAttribute(tf32_gemm<RELU, OMODE>,
                         cudaFuncAttributeMaxDynamicSharedMemorySize, GEMM_SMEM);
    dim3 g(N / 128, M / 128);
    tf32_gemm<RELU, OMODE><<<g, 512, GEMM_SMEM>>>(ah, al, bh, bl, bias, cf, chi, clo,
                                                  M, N, K);
}

extern "C" void kernel_launch(void* const* d_in, const int* in_sizes, int n_in,
                              void* d_out, int out_size)
{
    const float* x      = (const float*)d_in[0];
    const int*   labels = (const int*)  d_in[1];
    const float* ew[4]  = {(const float*)d_in[2], (const float*)d_in[4],
                           (const float*)d_in[6], (const float*)d_in[8]};
    const float* eb[4]  = {(const float*)d_in[3], (const float*)d_in[5],
                           (const float*)d_in[7], (const float*)d_in[9]};
    const float* dw[4]  = {(const float*)d_in[10], (const float*)d_in[12],
                           (const float*)d_in[14], (const float*)d_in[16]};
    const float* db[4]  = {(const float*)d_in[11], (const float*)d_in[13],
                           (const float*)d_in[15], (const float*)d_in[17]};
    const float* cb     = (const float*)d_in[18];
    float* out = (float*)d_out;

    float *buf0, *buf1, *res, *xq, *dAh, *dAl, *dBh, *dBl, *wh, *wl;
    cudaGetSymbolAddress((void**)&buf0, g_buf0);
    cudaGetSymbolAddress((void**)&buf1, g_buf1);
    cudaGetSymbolAddress((void**)&res,  g_res);
    cudaGetSymbolAddress((void**)&xq,   g_xq);
    cudaGetSymbolAddress((void**)&dAh,  g_dAh);
    cudaGetSymbolAddress((void**)&dAl,  g_dAl);
    cudaGetSymbolAddress((void**)&dBh,  g_dBh);
    cudaGetSymbolAddress((void**)&dBl,  g_dBl);
    cudaGetSymbolAddress((void**)&wh,   g_wh);
    cudaGetSymbolAddress((void**)&wl,   g_wl);

    static const int RQ_SMEM = CBK * 129 * sizeof(float);
    cudaFuncSetAttribute(rq_level, cudaFuncAttributeMaxDynamicSharedMemorySize, RQ_SMEM);

    // decoder weight table: Wt is [N,K]
    const int LN[4] = {512, 1024, 2048, 768};
    const int LK[4] = {128, 512, 1024, 2048};
    size_t woff[4];
    {
        size_t o = 0;
        for (int i = 0; i < 4; i++) { woff[i] = o; o += (size_t)LN[i] * LK[i]; }
    }

    // ---- preprocess decoder weights (transpose + tf32 hi/lo split) ----
    for (int i = 0; i < 4; i++) {
        dim3 g(LN[i] / 32, LK[i] / 32), b(32, 32);
        k_wprep32<<<g, b>>>(dw[i], wh + woff[i], wl + woff[i], LK[i], LN[i]);
    }

    // ---- expert grouping ----
    k_zero_counts<<<1, 32>>>();
    k_hist   <<<BROWS / 256, 256>>>(labels);
    k_scan   <<<1, 1>>>();
    k_scatter<<<BROWS / 256, 256>>>(labels);

    // ---- encoder (fp32 SIMT — flip-critical path) ----
    launch_sgemm<true >(x,    ew[0], eb[0], buf0, BROWS, 2048, 768);
    launch_sgemm<true >(buf0, ew[1], eb[1], buf1, BROWS, 1024, 2048);
    launch_sgemm<true >(buf1, ew[2], eb[2], buf0, BROWS, 512,  1024);
    launch_sgemm<false>(buf0, ew[3], eb[3], res,  BROWS, 128,  512);

    // ---- residual quantization ----
    k_rq_init<<<(BROWS * ZD + 255) / 256, 256>>>();
    dim3 rqg((BROWS + 31) / 32, NUM_EXPERTS);
    for (int l = 0; l < NUM_LEVELS; l++)
        rq_level<<<rqg, 256, RQ_SMEM>>>(cb, out + IDX_OFF, l);
    k_loss_finish<<<1, 1024>>>(out + LOSS_OFF);
    k_copy_xq<<<(BROWS * ZD + 255) / 256, 256>>>(out + XQ_OFF);

    // ---- decoder (3xTF32, pre-split operands, ldmatrix-fed) ----
    k_split32<<<(BROWS * ZD + 255) / 256, 256>>>(xq, dAh, dAl, BROWS * ZD);
    launch_tf32<true, 1>(dAh, dAl, wh + woff[0], wl + woff[0], db[0],
                         nullptr, dBh, dBl, BROWS, 512, 128);
    launch_tf32<true, 1>(dBh, dBl, wh + woff[1], wl + woff[1], db[1],
                         nullptr, dAh, dAl, BROWS, 1024, 512);
    launch_tf32<true, 1>(dAh, dAl, wh + woff[2], wl + woff[2], db[2],
                         nullptr, dBh, dBl, BROWS, 2048, 1024);
    launch_tf32<false, 0>(dBh, dBl, wh + woff[3], wl + woff[3], db[3],
                          out + OUT_OFF, nullptr, nullptr, BROWS, 768, 2048);
}

// round 7
// speedup vs baseline: 1.3251x; 1.1844x over previous
#include <cuda_runtime.h>
#include <cuda_bf16.h>
#include <cstdint>

// ---------------------------------------------------------------------------
// Problem constants
// ---------------------------------------------------------------------------
#define BROWS 32768
#define NUM_EXPERTS 10
#define NUM_LEVELS 4
#define CBK 256
#define ZD 128
#define BETA 0.001f

// Output layout (float32, tuple flattened: out, loss, indices, x_q)
#define OUT_OFF  0
#define LOSS_OFF (32768 * 768)
#define IDX_OFF  (LOSS_OFF + 1)
#define XQ_OFF   (IDX_OFF + 32768 * 4)

// ---------------------------------------------------------------------------
// Device scratch
// ---------------------------------------------------------------------------
__device__ float g_buf0[32768u * 2048u];   // encoder ping
__device__ float g_buf1[32768u * 1024u];   // encoder pong
__device__ float g_res [32768 * ZD];
__device__ float g_xq  [32768 * ZD];
__device__ float g_lossbuf[32768];
__device__ int   g_counts[NUM_EXPERTS];
__device__ int   g_cursor[NUM_EXPERTS];
__device__ int   g_offsets[NUM_EXPERTS + 1];
__device__ int   g_perm[32768];

// decoder bf16 hi/lo activation ping-pong + pre-split transposed weights
__device__ __nv_bfloat16 g_dAh[32768u * 1024u];
__device__ __nv_bfloat16 g_dAl[32768u * 1024u];
__device__ __nv_bfloat16 g_dBh[32768u * 2048u];
__device__ __nv_bfloat16 g_dBl[32768u * 2048u];
#define DW_TOTAL 4259840
__device__ __nv_bfloat16 g_wh[DW_TOTAL];
__device__ __nv_bfloat16 g_wl[DW_TOTAL];

// ---------------------------------------------------------------------------
// PTX helpers (arch-portable: cp.async sm_80+, ldmatrix sm_75+, bf16 mma sm_80+)
// ---------------------------------------------------------------------------
__device__ __forceinline__ uint32_t smem_u32(const void* p) {
    uint32_t a;
    asm("{ .reg .u64 t; cvta.to.shared.u64 t, %1; cvt.u32.u64 %0, t; }"
        : "=r"(a) : "l"(p));
    return a;
}
__device__ __forceinline__ void cpa16(uint32_t dst, const void* src) {
    asm volatile("cp.async.cg.shared.global [%0], [%1], 16;" :: "r"(dst), "l"(src) : "memory");
}
#define CP_COMMIT() asm volatile("cp.async.commit_group;" ::: "memory")
#define CP_WAIT1()  asm volatile("cp.async.wait_group 1;" ::: "memory")

#define LDSM4(r0, r1, r2, r3, addr) \
    asm volatile("ldmatrix.sync.aligned.m8n8.x4.shared.b16 {%0,%1,%2,%3}, [%4];" \
        : "=r"(r0), "=r"(r1), "=r"(r2), "=r"(r3) : "r"(addr))

#define MMA16816(acc, a, b0, b1) \
    asm volatile("mma.sync.aligned.m16n8k16.row.col.f32.bf16.bf16.f32 " \
        "{%0,%1,%2,%3}, {%4,%5,%6,%7}, {%8,%9}, {%0,%1,%2,%3};" \
        : "+f"((acc)[0]), "+f"((acc)[1]), "+f"((acc)[2]), "+f"((acc)[3]) \
        : "r"((a)[0]), "r"((a)[1]), "r"((a)[2]), "r"((a)[3]), "r"(b0), "r"(b1))

// ---------------------------------------------------------------------------
// fp32 SIMT SGEMM (validated round 1) — ENCODER (flip-critical path)
// ---------------------------------------------------------------------------
template <bool RELU>
__global__ __launch_bounds__(256, 2)
void sgemm_bias(const float* __restrict__ A, const float* __restrict__ W,
                const float* __restrict__ bias, float* __restrict__ C,
                int M, int N, int K)
{
    __shared__ float As[8][128];
    __shared__ float Bs[8][128];

    const int t  = threadIdx.x;
    const int bm = blockIdx.y;
    const int bn = blockIdx.x;
    const int tx = t & 15;
    const int ty = t >> 4;

    const int arow = t >> 1;
    const int acol = (t & 1) * 4;
    const float* Ag = A + (bm * 128 + arow) * K + acol;

    const int brow = t >> 5;
    const int bcol = (t & 31) * 4;
    const float* Wg = W + brow * N + bn * 128 + bcol;

    float acc[8][8];
#pragma unroll
    for (int i = 0; i < 8; i++)
#pragma unroll
        for (int j = 0; j < 8; j++) acc[i][j] = 0.f;

    for (int k0 = 0; k0 < K; k0 += 8) {
        float4 av = *(const float4*)(Ag + k0);
        float4 wv = *(const float4*)(Wg + k0 * N);

        As[acol + 0][arow] = av.x;
        As[acol + 1][arow] = av.y;
        As[acol + 2][arow] = av.z;
        As[acol + 3][arow] = av.w;
        *(float4*)&Bs[brow][bcol] = wv;
        __syncthreads();

#pragma unroll
        for (int k = 0; k < 8; k++) {
            float a[8], b[8];
            *(float4*)&a[0] = *(const float4*)&As[k][ty * 8];
            *(float4*)&a[4] = *(const float4*)&As[k][ty * 8 + 4];
            *(float4*)&b[0] = *(const float4*)&Bs[k][tx * 8];
            *(float4*)&b[4] = *(const float4*)&Bs[k][tx * 8 + 4];
#pragma unroll
            for (int i = 0; i < 8; i++)
#pragma unroll
                for (int j = 0; j < 8; j++)
                    acc[i][j] += a[i] * b[j];
        }
        __syncthreads();
    }

    const int crow0 = bm * 128 + ty * 8;
    const int ccol0 = bn * 128 + tx * 8;
    float bb[8];
#pragma unroll
    for (int j = 0; j < 8; j++) bb[j] = bias[ccol0 + j];

#pragma unroll
    for (int i = 0; i < 8; i++) {
        float v[8];
#pragma unroll
        for (int j = 0; j < 8; j++) {
            float x = acc[i][j] + bb[j];
            if (RELU) x = fmaxf(x, 0.f);
            v[j] = x;
        }
        float* cp = C + (crow0 + i) * N + ccol0;
        *(float4*)(cp)     = *(float4*)&v[0];
        *(float4*)(cp + 4) = *(float4*)&v[4];
    }
}

// ---------------------------------------------------------------------------
// HMMA bf16x3 GEMM — DECODER (downstream of quantization; smooth error only).
// A given as bf16 hi/lo [M,K]; W pre-transposed+split to [N,K] hi/lo.
// Tile: 128x128, BK=32, 256 threads (8 warps, each 32 rows x 64 cols).
// Smem: padded K-stride 40 bf16 (80B rows) -> conflict-free ldmatrix.
// OMODE 0: fp32 C.  OMODE 1: bf16 hi/lo split C (feeds next layer).
// ---------------------------------------------------------------------------
#define TSTRIDE 40                       // bf16 elements per smem row
#define SUBTILE (128 * TSTRIDE * 2)      // bytes per subtile (10240)
#define STAGEB  (4 * SUBTILE)            // Ahi,Alo,Bhi,Blo per stage (40960)
#define GEMM_SMEM (2 * STAGEB)           // 81920

template <bool RELU, int OMODE>
__global__ __launch_bounds__(256)
void hmma_gemm(const __nv_bfloat16* __restrict__ Ahi, const __nv_bfloat16* __restrict__ Alo,
               const __nv_bfloat16* __restrict__ Bhi, const __nv_bfloat16* __restrict__ Blo,
               const float* __restrict__ bias,
               float* __restrict__ Cf,
               __nv_bfloat16* __restrict__ Chi, __nv_bfloat16* __restrict__ Clo,
               int M, int N, int K)
{
    extern __shared__ char smem[];
    const uint32_t sbase = smem_u32(smem);
    const int tid  = threadIdx.x;
    const int lane = tid & 31;
    const int wid  = tid >> 5;
    const int wm   = wid & 3;            // 4 warp-rows of 32
    const int wn   = wid >> 2;           // 2 warp-cols of 64
    const int m0   = blockIdx.y * 128;
    const int n0   = blockIdx.x * 128;
    const int nch  = K >> 5;             // K-chunks of 32

    float acc[2][8][4];
#pragma unroll
    for (int a = 0; a < 2; a++)
#pragma unroll
        for (int b = 0; b < 8; b++)
#pragma unroll
            for (int c = 0; c < 4; c++) acc[a][b][c] = 0.f;

#define LOAD_STAGE(stg, k0_) do {                                              \
        uint32_t sb_ = sbase + (stg) * STAGEB;                                 \
        for (int i = tid; i < 512; i += 256) {                                 \
            int r_ = i >> 2, c_ = i & 3;                                       \
            uint32_t so_ = r_ * 80 + c_ * 16;                                  \
            size_t ga_ = (size_t)(m0 + r_) * K + (k0_) + c_ * 8;               \
            size_t gb_ = (size_t)(n0 + r_) * K + (k0_) + c_ * 8;               \
            cpa16(sb_ + so_,               Ahi + ga_);                         \
            cpa16(sb_ + SUBTILE + so_,     Alo + ga_);                         \
            cpa16(sb_ + 2 * SUBTILE + so_, Bhi + gb_);                         \
            cpa16(sb_ + 3 * SUBTILE + so_, Blo + gb_);                         \
        }                                                                      \
    } while (0)

    LOAD_STAGE(0, 0);
    CP_COMMIT();
    if (nch > 1) LOAD_STAGE(1, 32);
    CP_COMMIT();

    const int lrow = lane & 15;
    const int lsel = (lane >> 4) << 3;

    for (int ch = 0; ch < nch; ch++) {
        CP_WAIT1();
        __syncthreads();
        const uint32_t sb = sbase + (ch & 1) * STAGEB;
        const uint32_t Ahb = sb, Alb = sb + SUBTILE;
        const uint32_t Bhb = sb + 2 * SUBTILE, Blb = sb + 3 * SUBTILE;

#pragma unroll
        for (int kk = 0; kk < 32; kk += 16) {
            uint32_t ah[2][4], al[2][4];
#pragma unroll
            for (int mt = 0; mt < 2; mt++) {
                uint32_t off = ((wm * 32 + mt * 16 + lrow) * TSTRIDE + kk + lsel) * 2;
                LDSM4(ah[mt][0], ah[mt][1], ah[mt][2], ah[mt][3], Ahb + off);
                LDSM4(al[mt][0], al[mt][1], al[mt][2], al[mt][3], Alb + off);
            }
            uint32_t bh[8][2], bl[8][2];
#pragma unroll
            for (int g = 0; g < 4; g++) {
                uint32_t off = ((wn * 64 + g * 16 + lrow) * TSTRIDE + kk + lsel) * 2;
                uint32_t t0, t1, t2, t3;
                LDSM4(t0, t1, t2, t3, Bhb + off);
                bh[2*g][0] = t0; bh[2*g][1] = t2;
                bh[2*g+1][0] = t1; bh[2*g+1][1] = t3;
                LDSM4(t0, t1, t2, t3, Blb + off);
                bl[2*g][0] = t0; bl[2*g][1] = t2;
                bl[2*g+1][0] = t1; bl[2*g+1][1] = t3;
            }
            // 3-pass emulated: hh + hl + lh
#pragma unroll
            for (int mt = 0; mt < 2; mt++)
#pragma unroll
                for (int nt = 0; nt < 8; nt++) {
                    MMA16816(acc[mt][nt], ah[mt], bh[nt][0], bh[nt][1]);
                    MMA16816(acc[mt][nt], ah[mt], bl[nt][0], bl[nt][1]);
                    MMA16816(acc[mt][nt], al[mt], bh[nt][0], bh[nt][1]);
                }
        }
        __syncthreads();
        if (ch + 2 < nch) LOAD_STAGE(ch & 1, (ch + 2) * 32);
        CP_COMMIT();
    }
#undef LOAD_STAGE

    // ---- epilogue ----
    const int gid = lane >> 2;
    const int tg  = lane & 3;
#pragma unroll
    for (int mt = 0; mt < 2; mt++) {
#pragma unroll
        for (int nt = 0; nt < 8; nt++) {
            const int col = n0 + wn * 64 + nt * 8 + tg * 2;
            const float2 bb = __ldg((const float2*)(bias + col));
#pragma unroll
            for (int h = 0; h < 2; h++) {
                const int row = m0 + wm * 32 + mt * 16 + gid + h * 8;
                float v0 = acc[mt][nt][2*h]   + bb.x;
                float v1 = acc[mt][nt][2*h+1] + bb.y;
                if (RELU) { v0 = fmaxf(v0, 0.f); v1 = fmaxf(v1, 0.f); }
                if (OMODE == 0) {
                    *(float2*)(Cf + (size_t)row * N + col) = make_float2(v0, v1);
                } else {
                    __nv_bfloat16 h0 = __float2bfloat16(v0);
                    __nv_bfloat16 h1 = __float2bfloat16(v1);
                    __nv_bfloat162 hh; hh.x = h0; hh.y = h1;
                    __nv_bfloat162 ll;
                    ll.x = __float2bfloat16(v0 - __bfloat162float(h0));
                    ll.y = __float2bfloat16(v1 - __bfloat162float(h1));
                    *(__nv_bfloat162*)(Chi + (size_t)row * N + col) = hh;
                    *(__nv_bfloat162*)(Clo + (size_t)row * N + col) = ll;
                }
            }
        }
    }
}

// ---------------------------------------------------------------------------
// Preprocessing: weight transpose + bf16 split; activation split
// ---------------------------------------------------------------------------
__global__ void k_wprep(const float* __restrict__ W, __nv_bfloat16* __restrict__ Th,
                        __nv_bfloat16* __restrict__ Tl, int K, int N)
{
    __shared__ float t[32][33];
    int n = blockIdx.x * 32 + threadIdx.x;
    int k = blockIdx.y * 32 + threadIdx.y;
    t[threadIdx.y][threadIdx.x] = W[(size_t)k * N + n];
    __syncthreads();
    int nn = blockIdx.x * 32 + threadIdx.y;
    int kk = blockIdx.y * 32 + threadIdx.x;
    float v = t[threadIdx.x][threadIdx.y];
    __nv_bfloat16 h = __float2bfloat16(v);
    Th[(size_t)nn * K + kk] = h;
    Tl[(size_t)nn * K + kk] = __float2bfloat16(v - __bfloat162float(h));
}

__global__ void k_split(const float* __restrict__ src, __nv_bfloat16* __restrict__ hi,
                        __nv_bfloat16* __restrict__ lo, int n)
{
    int i = blockIdx.x * 256 + threadIdx.x;
    if (i < n) {
        float v = src[i];
        __nv_bfloat16 h = __float2bfloat16(v);
        hi[i] = h;
        lo[i] = __float2bfloat16(v - __bfloat162float(h));
    }
}

// ---------------------------------------------------------------------------
// Expert counting-sort
// ---------------------------------------------------------------------------
__global__ void k_zero_counts() {
    int t = threadIdx.x;
    if (t < NUM_EXPERTS) { g_counts[t] = 0; g_cursor[t] = 0; }
}
__global__ void k_hist(const int* __restrict__ labels) {
    int i = blockIdx.x * blockDim.x + threadIdx.x;
    if (i < BROWS) atomicAdd(&g_counts[labels[i]], 1);
}
__global__ void k_scan() {
    if (threadIdx.x == 0) {
        int s = 0;
        for (int e = 0; e < NUM_EXPERTS; e++) { g_offsets[e] = s; s += g_counts[e]; }
        g_offsets[NUM_EXPERTS] = s;
    }
}
__global__ void k_scatter(const int* __restrict__ labels) {
    int i = blockIdx.x * blockDim.x + threadIdx.x;
    if (i < BROWS) {
        int e = labels[i];
        int p = atomicAdd(&g_cursor[e], 1);
        g_perm[g_offsets[e] + p] = i;
    }
}
__global__ void k_rq_init() {
    int i = blockIdx.x * blockDim.x + threadIdx.x;
    if (i < BROWS * ZD) g_xq[i] = 0.f;
    if (i < BROWS)      g_lossbuf[i] = 0.f;
}

// ---------------------------------------------------------------------------
// Residual quantization (validated round 1)
// ---------------------------------------------------------------------------
__global__ void rq_level(const float* __restrict__ cb,
                         float* __restrict__ idx_out, int level)
{
    extern __shared__ float c_sh[];        // 256 * 129 floats
    __shared__ float res_sh[ZD];
    __shared__ float cn_sh[CBK];
    __shared__ float s_sc[CBK];
    __shared__ int   s_ix[CBK];
    __shared__ float s_red[4];
    __shared__ int   s_kmin;

    const int e     = blockIdx.y;
    const int start = g_offsets[e];
    const int end   = g_offsets[e + 1];
    const int rbase = start + blockIdx.x * 32;
    if (rbase >= end) return;

    const int t = threadIdx.x;
    const float* cbl = cb + ((size_t)level * NUM_EXPERTS + e) * CBK * ZD;
    for (int i = t; i < (CBK * ZD) / 4; i += 256) {
        float4 v = ((const float4*)cbl)[i];
        int k = i >> 5;
        int j = (i & 31) << 2;
        float* d = &c_sh[k * 129 + j];
        d[0] = v.x; d[1] = v.y; d[2] = v.z; d[3] = v.w;
    }
    __syncthreads();

    {
        const float* cr = &c_sh[t * 129];
        float s = 0.f;
#pragma unroll 8
        for (int j = 0; j < ZD; j++) s += cr[j] * cr[j];
        cn_sh[t] = s;
    }
    __syncthreads();

    const int nrows = min(32, end - rbase);
    for (int i = 0; i < nrows; i++) {
        const int row = g_perm[rbase + i];
        if (t < ZD) res_sh[t] = g_res[row * ZD + t];
        __syncthreads();

        float dot = 0.f;
        const float* cr = &c_sh[t * 129];
#pragma unroll 8
        for (int j = 0; j < ZD; j++) dot += cr[j] * res_sh[j];
        s_sc[t] = cn_sh[t] - 2.f * dot;
        s_ix[t] = t;
        __syncthreads();

#pragma unroll
        for (int s = 128; s > 0; s >>= 1) {
            if (t < s) {
                float sc2 = s_sc[t + s]; int ix2 = s_ix[t + s];
                if (sc2 < s_sc[t] || (sc2 == s_sc[t] && ix2 < s_ix[t])) {
                    s_sc[t] = sc2; s_ix[t] = ix2;
                }
            }
            __syncthreads();
        }
        if (t == 0) s_kmin = s_ix[0];
        __syncthreads();
        const int kmin = s_kmin;

        float sq = 0.f;
        if (t < ZD) {
            float q  = c_sh[kmin * 129 + t];
            float nr = res_sh[t] - q;
            g_res[row * ZD + t] = nr;
            g_xq [row * ZD + t] += q;
            sq = nr * nr;
        }
#pragma unroll
        for (int o = 16; o > 0; o >>= 1) sq += __shfl_down_sync(0xffffffffu, sq, o);
        if (t < ZD && (t & 31) == 0) s_red[t >> 5] = sq;
        __syncthreads();
        if (t == 0) {
            g_lossbuf[row] += s_red[0] + s_red[1] + s_red[2] + s_red[3];
            idx_out[row * 4 + level] = (float)kmin;
        }
        __syncthreads();
    }
}

__global__ void k_loss_finish(float* __restrict__ loss_out) {
    __shared__ float sm[1024];
    float s = 0.f;
    for (int i = threadIdx.x; i < BROWS; i += 1024) s += g_lossbuf[i];
    sm[threadIdx.x] = s;
    __syncthreads();
    for (int k = 512; k > 0; k >>= 1) {
        if (threadIdx.x < k) sm[threadIdx.x] += sm[threadIdx.x + k];
        __syncthreads();
    }
    if (threadIdx.x == 0)
        loss_out[0] = sm[0] * (1.f + BETA) / ((float)BROWS * (float)ZD);
}

__global__ void k_copy_xq(float* __restrict__ dst) {
    int i = blockIdx.x * blockDim.x + threadIdx.x;
    if (i < BROWS * ZD) dst[i] = g_xq[i];
}

// ---------------------------------------------------------------------------
// Host launch
// ---------------------------------------------------------------------------
template <bool RELU>
static void launch_sgemm(const float* A, const float* W, const float* b, float* C,
                         int M, int N, int K)
{
    dim3 grid(N / 128, M / 128);
    sgemm_bias<RELU><<<grid, 256>>>(A, W, b, C, M, N, K);
}

template <bool RELU, int OMODE>
static void launch_hmma(const __nv_bfloat16* ah, const __nv_bfloat16* al,
                        const __nv_bfloat16* bh, const __nv_bfloat16* bl,
                        const float* bias, float* cf,
                        __nv_bfloat16* ch, __nv_bfloat16* cl,
                        int M, int N, int K)
{
    cudaFuncSetAttribute(hmma_gemm<RELU, OMODE>,
                         cudaFuncAttributeMaxDynamicSharedMemorySize, GEMM_SMEM);
    dim3 g(N / 128, M / 128);
    hmma_gemm<RELU, OMODE><<<g, 256, GEMM_SMEM>>>(ah, al, bh, bl, bias, cf, ch, cl, M, N, K);
}

extern "C" void kernel_launch(void* const* d_in, const int* in_sizes, int n_in,
                              void* d_out, int out_size)
{
    const float* x      = (const float*)d_in[0];
    const int*   labels = (const int*)  d_in[1];
    const float* ew[4]  = {(const float*)d_in[2], (const float*)d_in[4],
                           (const float*)d_in[6], (const float*)d_in[8]};
    const float* eb[4]  = {(const float*)d_in[3], (const float*)d_in[5],
                           (const float*)d_in[7], (const float*)d_in[9]};
    const float* dw[4]  = {(const float*)d_in[10], (const float*)d_in[12],
                           (const float*)d_in[14], (const float*)d_in[16]};
    const float* db[4]  = {(const float*)d_in[11], (const float*)d_in[13],
                           (const float*)d_in[15], (const float*)d_in[17]};
    const float* cb     = (const float*)d_in[18];
    float* out = (float*)d_out;

    float *buf0, *buf1, *res, *xq;
    __nv_bfloat16 *dAh, *dAl, *dBh, *dBl, *wh, *wl;
    cudaGetSymbolAddress((void**)&buf0, g_buf0);
    cudaGetSymbolAddress((void**)&buf1, g_buf1);
    cudaGetSymbolAddress((void**)&res,  g_res);
    cudaGetSymbolAddress((void**)&xq,   g_xq);
    cudaGetSymbolAddress((void**)&dAh,  g_dAh);
    cudaGetSymbolAddress((void**)&dAl,  g_dAl);
    cudaGetSymbolAddress((void**)&dBh,  g_dBh);
    cudaGetSymbolAddress((void**)&dBl,  g_dBl);
    cudaGetSymbolAddress((void**)&wh,   g_wh);
    cudaGetSymbolAddress((void**)&wl,   g_wl);

    static const int RQ_SMEM = CBK * 129 * sizeof(float);
    cudaFuncSetAttribute(rq_level, cudaFuncAttributeMaxDynamicSharedMemorySize, RQ_SMEM);

    // decoder weight table: Wt is [N,K]
    const int LN[4] = {512, 1024, 2048, 768};
    const int LK[4] = {128, 512, 1024, 2048};
    size_t woff[4];
    {
        size_t o = 0;
        for (int i = 0; i < 4; i++) { woff[i] = o; o += (size_t)LN[i] * LK[i]; }
    }

    // ---- preprocess decoder weights (transpose + bf16 hi/lo split) ----
    for (int i = 0; i < 4; i++) {
        dim3 g(LN[i] / 32, LK[i] / 32), b(32, 32);
        k_wprep<<<g, b>>>(dw[i], wh + woff[i], wl + woff[i], LK[i], LN[i]);
    }

    // ---- expert grouping ----
    k_zero_counts<<<1, 32>>>();
    k_hist   <<<BROWS / 256, 256>>>(labels);
    k_scan   <<<1, 1>>>();
    k_scatter<<<BROWS / 256, 256>>>(labels);

    // ---- encoder (fp32 SIMT — flip-critical path) ----
    launch_sgemm<true >(x,    ew[0], eb[0], buf0, BROWS, 2048, 768);
    launch_sgemm<true >(buf0, ew[1], eb[1], buf1, BROWS, 1024, 2048);
    launch_sgemm<true >(buf1, ew[2], eb[2], buf0, BROWS, 512,  1024);
    launch_sgemm<false>(buf0, ew[3], eb[3], res,  BROWS, 128,  512);

    // ---- residual quantization ----
    k_rq_init<<<(BROWS * ZD + 255) / 256, 256>>>();
    dim3 rqg((BROWS + 31) / 32, NUM_EXPERTS);
    for (int l = 0; l < NUM_LEVELS; l++)
        rq_level<<<rqg, 256, RQ_SMEM>>>(cb, out + IDX_OFF, l);
    k_loss_finish<<<1, 1024>>>(out + LOSS_OFF);
    k_copy_xq<<<(BROWS * ZD + 255) / 256, 256>>>(out + XQ_OFF);

    // ---- decoder (bf16x3 legacy HMMA — 2x the tf32 legacy rate) ----
    k_split<<<(BROWS * ZD + 255) / 256, 256>>>(xq, dAh, dAl, BROWS * ZD);
    launch_hmma<true, 1>(dAh, dAl, wh + woff[0], wl + woff[0], db[0],
                         nullptr, dBh, dBl, BROWS, 512, 128);
    launch_hmma<true, 1>(dBh, dBl, wh + woff[1], wl + woff[1], db[1],
                         nullptr, dAh, dAl, BROWS, 1024, 512);
    launch_hmma<true, 1>(dAh, dAl, wh + woff[2], wl + woff[2], db[2],
                         nullptr, dBh, dBl, BROWS, 2048, 1024);
    launch_hmma<false, 0>(dBh, dBl, wh + woff[3], wl + woff[3], db[3],
                          out + OUT_OFF, nullptr, nullptr, BROWS, 768, 2048);
}